// round 15
// baseline (speedup 1.0000x reference)
#include <cuda_runtime.h>
#include <math.h>
#include <stdint.h>

#define Bv 4
#define Tv 2048
#define Cv 1024
#define Hv 16
#define Dv 64
#define Mrows (Bv*Tv)   // 8192

// ---------------- scratch (device globals; allocation-free) ----------------
__device__ float g_q[Bv*Hv*Tv*Dv];    // [B,H,T,D] (tf32-rounded)
__device__ float g_k[Bv*Hv*Tv*Dv];    // [B,H,T,D]
__device__ float g_v[Bv*Hv*Tv*Dv];    // [B,H,T,D]
__device__ float g_y[Bv*Tv*Cv];       // attention output [B,T,C] (tf32-rounded)
__device__ float g_xr[Mrows*Cv];      // x, tf32-rounded
__device__ float g_wqT[3*Cv*Cv];      // W_qkv^T [3072][1024], tf32-rounded
__device__ float g_woT[Cv*Cv];        // W_out^T [1024][1024], tf32-rounded
__device__ int   g_flag[1536];        // per-gemm-tile done flags (bx*64+by)
__device__ int   g_qhead;             // gemm tile queue
__device__ int   g_ahead;             // attention job queue

__device__ __forceinline__ float rna_tf32(float x) {
    uint32_t u;
    asm("cvt.rna.tf32.f32 %0, %1;" : "=r"(u) : "f"(x));
    return __uint_as_float(u);
}

__device__ __forceinline__ void mma16n8k8(float* c, const uint32_t* a, const uint32_t* b) {
    asm volatile(
        "mma.sync.aligned.m16n8k8.row.col.f32.tf32.tf32.f32 "
        "{%0,%1,%2,%3}, {%4,%5,%6,%7}, {%8,%9}, {%0,%1,%2,%3};"
        : "+f"(c[0]), "+f"(c[1]), "+f"(c[2]), "+f"(c[3])
        : "r"(a[0]), "r"(a[1]), "r"(a[2]), "r"(a[3]), "r"(b[0]), "r"(b[1]));
}

__device__ __forceinline__ void ldsm_x4(uint32_t* r, uint32_t addr) {
    asm volatile(
        "ldmatrix.sync.aligned.m8n8.x4.shared.b16 {%0,%1,%2,%3}, [%4];"
        : "=r"(r[0]), "=r"(r[1]), "=r"(r[2]), "=r"(r[3]) : "r"(addr));
}

__device__ __forceinline__ void cp_async16(uint32_t dst, const float* src) {
    asm volatile("cp.async.cg.shared.global [%0], [%1], 16;" :: "r"(dst), "l"(src) : "memory");
}

// lane-0 spins with acquire; warp rejoins.
__device__ __forceinline__ void wait_flag(const int* f) {
    if ((threadIdx.x & 31) == 0) {
        int v;
        do {
            asm volatile("ld.acquire.gpu.b32 %0, [%1];" : "=r"(v) : "l"(f) : "memory");
            if (!v) __nanosleep(200);
        } while (!v);
    }
    __syncwarp();
}

// gemm tile queue order: [q mt=15][kv mt'=0][q 14][kv 1] ... (96 per super-block)
__device__ __forceinline__ void sched_tile(int t, int& bx, int& by) {
    const int j = t / 96, r = t - j * 96;
    if (r < 32) { bx = r & 7;             by = (r >> 3) * 16 + (15 - j); }
    else        { const int i2 = r - 32;  bx = 8 + (i2 & 15); by = (i2 >> 4) * 16 + j; }
}

#define BAR1() asm volatile("bar.sync 1, 128;" ::: "memory")

// ---------------- prep kernels ----------------
__global__ void zero_sched_kernel() {
    const int i = blockIdx.x * blockDim.x + threadIdx.x;
    if (i < 1536) g_flag[i] = 0;
    if (i == 1536) g_qhead = 0;
    if (i == 1537) g_ahead = 0;
}
__global__ void round_rna_kernel(const float4* __restrict__ src, float4* __restrict__ dst, int n4) {
    for (int i = blockIdx.x * blockDim.x + threadIdx.x; i < n4; i += gridDim.x * blockDim.x) {
        float4 v = src[i];
        v.x = rna_tf32(v.x); v.y = rna_tf32(v.y);
        v.z = rna_tf32(v.z); v.w = rna_tf32(v.w);
        dst[i] = v;
    }
}
__global__ void transpose_rna_kernel(const float* __restrict__ src, float* __restrict__ dst,
                                     int K, int N) {
    __shared__ float t[32][33];
    int n0 = blockIdx.x * 32, k0 = blockIdx.y * 32;
    #pragma unroll
    for (int i = 0; i < 32; i += 8)
        t[threadIdx.y + i][threadIdx.x] =
            src[(size_t)(k0 + threadIdx.y + i) * N + n0 + threadIdx.x];
    __syncthreads();
    #pragma unroll
    for (int i = 0; i < 32; i += 8)
        dst[(size_t)(n0 + threadIdx.y + i) * K + k0 + threadIdx.x] =
            rna_tf32(t[threadIdx.x][threadIdx.y + i]);
}

// ---------------- tile geometry ----------------
#define BK 32
#define LDW 36
#define NSTG 3
#define TILEW (128*LDW)
#define GEMM_SMEM (NSTG * 2 * TILEW * 4)      // 110592 B

#define ALD 68
#define VLD 72
#define KVSTG (64*ALD + 64*VLD)
#define ATTN_SMEM ((128*ALD + 2*KVSTG) * 4)   // 106496 B
#define FUSED_SMEM GEMM_SMEM                  // max of the two
#define NSLOTS 296

// ---------------------------------------------------------------------------
// FUSED persistent kernel: phase 1 = QKV gemm tiles (atomic queue, 8 warps),
// phase 2 = flash attention jobs (atomic queue, warps 0-3, flag-gated).
// ---------------------------------------------------------------------------
__global__ void __launch_bounds__(256, 2) fused_kernel(
    const float* __restrict__ xr, const float* __restrict__ wqT,
    const float* __restrict__ b_qkv)
{
    extern __shared__ float smg[];
    __shared__ int s_work;

    const int tid  = threadIdx.x;
    const int lane = tid & 31;
    const int g    = lane >> 2;
    const int tg   = lane & 3;

    // ============== PHASE 1: gemm<0> tiles ==============
    {
        float* As = smg;
        float* Bs = smg + NSTG * TILEW;

        const int wid = tid >> 5;
        const int wm  = (wid & 1) * 64;
        const int wn  = (wid >> 1) * 32;
        const int gr  = tid >> 3;
        const int gc  = (tid & 7) << 2;

        const uint32_t aBase = (uint32_t)__cvta_generic_to_shared(As);
        const uint32_t bBase = (uint32_t)__cvta_generic_to_shared(Bs);

        const int lrow  = lane & 15;
        const int lcolw = (lane >> 4) << 2;
        const int brow  = (lane & 7) + ((lane & 16) ? 8 : 0);
        const int bcolw = ((lane >> 3) & 1) << 2;
        const uint32_t aFragBase = aBase + (uint32_t)(((wm + lrow) * LDW + lcolw) * 4);
        const uint32_t bFragBase = bBase + (uint32_t)(((wn + brow) * LDW + bcolw) * 4);

        const int NC = Cv / BK;   // 32

        for (;;) {
            __syncthreads();                 // smem-stage + s_work reuse guard
            if (tid == 0) s_work = atomicAdd(&g_qhead, 1);
            __syncthreads();
            const int t = s_work;
            if (t >= 1536) break;

            int bx, by;
            sched_tile(t, bx, by);
            const int row0 = by * 128;
            const int col0 = bx * 128;
            const float* Ab = xr  + (size_t)row0 * Cv;
            const float* Bb = wqT + (size_t)col0 * Cv;

            float c[4][4][4];
            #pragma unroll
            for (int mt = 0; mt < 4; mt++)
                #pragma unroll
                for (int nt = 0; nt < 4; nt++)
                    #pragma unroll
                    for (int i = 0; i < 4; i++) c[mt][nt][i] = 0.f;

            auto issue = [&](int ch) {
                if (ch < NC) {
                    const int s = ch % NSTG;
                    const float* gA = Ab + ch * BK;
                    const float* gB = Bb + ch * BK;
                    const uint32_t ab = aBase + (uint32_t)(s * TILEW * 4);
                    const uint32_t bb = bBase + (uint32_t)(s * TILEW * 4);
                    #pragma unroll
                    for (int i = 0; i < 4; i++) {
                        const int r = gr + i * 32;
                        const uint32_t off = (uint32_t)((r * LDW + gc) * 4);
                        cp_async16(ab + off, gA + (size_t)r * Cv + gc);
                        cp_async16(bb + off, gB + (size_t)r * Cv + gc);
                    }
                }
                asm volatile("cp.async.commit_group;" ::: "memory");
            };

            issue(0);
            issue(1);

            for (int ch = 0; ch < NC; ch++) {
                asm volatile("cp.async.wait_group 1;" ::: "memory");
                __syncthreads();
                issue(ch + 2);

                const int s = ch % NSTG;
                const uint32_t aStage = aFragBase + (uint32_t)(s * TILEW * 4);
                const uint32_t bStage = bFragBase + (uint32_t)(s * TILEW * 4);

                #pragma unroll
                for (int ks = 0; ks < 4; ks++) {
                    uint32_t a[4][4];
                    #pragma unroll
                    for (int mt = 0; mt < 4; mt++)
                        ldsm_x4(a[mt], aStage + (uint32_t)(mt * 16 * LDW * 4 + ks * 32));
                    uint32_t b[2][4];
                    #pragma unroll
                    for (int ntp = 0; ntp < 2; ntp++)
                        ldsm_x4(b[ntp], bStage + (uint32_t)(ntp * 16 * LDW * 4 + ks * 32));
                    #pragma unroll
                    for (int mt = 0; mt < 4; mt++)
                        #pragma unroll
                        for (int nt = 0; nt < 4; nt++)
                            mma16n8k8(c[mt][nt], a[mt], b[nt >> 1] + (nt & 1) * 2);
                }
            }

            // epilogue: rounded scatter into g_q/g_k/g_v
            #pragma unroll
            for (int mt = 0; mt < 4; mt++) {
                #pragma unroll
                for (int r2 = 0; r2 < 2; r2++) {
                    const int row = row0 + wm + mt * 16 + g + r2 * 8;
                    const int b_ = row >> 11, t_ = row & 2047;
                    #pragma unroll
                    for (int nt = 0; nt < 4; nt++) {
                        const int col = col0 + wn + nt * 8 + tg * 2;
                        float2 v;
                        v.x = rna_tf32(c[mt][nt][r2 * 2 + 0] + __ldg(b_qkv + col + 0));
                        v.y = rna_tf32(c[mt][nt][r2 * 2 + 1] + __ldg(b_qkv + col + 1));
                        const int which = col >> 10;
                        const int cc = col & 1023;
                        const int h = cc >> 6, d = cc & 63;
                        float* dst = (which == 0) ? g_q : (which == 1) ? g_k : g_v;
                        *(float2*)&dst[((size_t)((b_ * Hv + h) * Tv + t_)) * Dv + d] = v;
                    }
                }
            }

            __threadfence();
            __syncthreads();
            if (tid == 0)
                asm volatile("st.release.gpu.b32 [%0], %1;"
                             :: "l"(g_flag + bx * 64 + by), "r"(1) : "memory");
        }
    }

    // ============== PHASE 2: attention jobs (warps 0-3 only) ==============
    if (tid >= 128) return;

    float* QP = smg;                   // [128][68]: Q then P staging
    float* KV = smg + 128 * ALD;

    const uint32_t qpBase = (uint32_t)__cvta_generic_to_shared(QP);
    const uint32_t kvBase = (uint32_t)__cvta_generic_to_shared(KV);

    const int w = tid >> 5;            // 0..3
    const int wrow = 32 * w;
    const int lrow  = lane & 15;
    const int lcolw = (lane >> 4) << 2;
    const int brow  = (lane & 7) + ((lane & 16) ? 8 : 0);
    const int bcolw = ((lane >> 3) & 1) << 2;
    const uint32_t pFragBase = qpBase + (uint32_t)(((wrow + lrow) * ALD + lcolw) * 4);

    const float QSCALE = 0.125f * 1.4426950408889634f;   // log2(e)/8

    for (;;) {
        BAR1();                          // QP/s_work reuse guard
        if (tid == 0) s_work = atomicAdd(&g_ahead, 1);
        BAR1();
        const int p = s_work;
        if (p >= 1024) return;

        const int m0 = (15 - (p >> 6)) * 128;   // heavy jobs first
        const int bh = p & 63;
        const int b_ = bh >> 4;
        const int h  = bh & 15;
        const int h2 = h >> 1;
        const int mt = m0 >> 7;

        const float* qp = g_q + (size_t)bh * Tv * Dv;
        const float* kp = g_k + (size_t)bh * Tv * Dv;
        const float* vp = g_v + (size_t)bh * Tv * Dv;

        auto issue_kv = [&](int kt) {
            const int s = kt & 1;
            const float* kpt = kp + (size_t)(kt * 64) * Dv;
            const float* vpt = vp + (size_t)(kt * 64) * Dv;
            const uint32_t kb = kvBase + (uint32_t)(s * KVSTG * 4);
            const uint32_t vb = kb + (uint32_t)(64 * ALD * 4);
            #pragma unroll
            for (int i = 0; i < 8; i++) {
                const int f = i * 128 + tid;
                const int rr = f >> 4, c4 = (f & 15) << 2;
                cp_async16(kb + (uint32_t)((rr * ALD + c4) * 4), kpt + rr * Dv + c4);
                cp_async16(vb + (uint32_t)((rr * VLD + c4) * 4), vpt + rr * Dv + c4);
            }
            asm volatile("cp.async.commit_group;" ::: "memory");
        };

        // producer gates: q tile + kv row-block 0
        wait_flag(g_flag + h2 * 64 + b_ * 16 + mt);
        wait_flag(g_flag + (8 + h2) * 64 + b_ * 16);
        wait_flag(g_flag + (16 + h2) * 64 + b_ * 16);

        issue_kv(0);

        // Load Q tile, scale by log2(e)/8, re-round to tf32.
        #pragma unroll
        for (int i = 0; i < 16; i++) {
            const int f = i * 128 + tid;
            const int rr = f >> 4, c4 = (f & 15) << 2;
            float4 v = *(const float4*)(qp + (size_t)(m0 + rr) * Dv + c4);
            v.x = rna_tf32(v.x * QSCALE);
            v.y = rna_tf32(v.y * QSCALE);
            v.z = rna_tf32(v.z * QSCALE);
            v.w = rna_tf32(v.w * QSCALE);
            *(float4*)&QP[rr * ALD + c4] = v;
        }
        BAR1();

        // Hoist Q fragments; QP becomes P staging afterwards.
        uint32_t qf[2][8][4];
        #pragma unroll
        for (int ks = 0; ks < 8; ks++) {
            ldsm_x4(qf[0][ks], pFragBase + (uint32_t)(ks * 32));
            ldsm_x4(qf[1][ks], pFragBase + (uint32_t)(16 * ALD * 4 + ks * 32));
        }

        float m_i[4] = {-1e30f, -1e30f, -1e30f, -1e30f};
        float l_i[4] = {0.f, 0.f, 0.f, 0.f};
        float o[2][8][4];
        #pragma unroll
        for (int rc = 0; rc < 2; rc++)
            #pragma unroll
            for (int nt = 0; nt < 8; nt++)
                #pragma unroll
                for (int e = 0; e < 4; e++) o[rc][nt][e] = 0.f;

        const int nkt = m0 / 64 + 2;
        for (int kt = 0; kt < nkt; kt++) {
            const int j0 = kt * 64;
            asm volatile("cp.async.wait_group 0;" ::: "memory");
            BAR1();
            if (kt + 1 < nkt) {
                if (((kt + 1) & 1) == 0) {
                    const int rb = (kt + 1) >> 1;
                    wait_flag(g_flag + (8 + h2) * 64 + b_ * 16 + rb);
                    wait_flag(g_flag + (16 + h2) * 64 + b_ * 16 + rb);
                }
                issue_kv(kt + 1);
            }

            const int s = kt & 1;
            const uint32_t kFragBase = kvBase + (uint32_t)(s * KVSTG * 4)
                                     + (uint32_t)((brow * ALD + bcolw) * 4);
            const uint32_t* Vsu = (const uint32_t*)(KV + s * KVSTG + 64 * ALD);

            // ---- S = Q @ K^T (log2 domain) ----
            float sacc[2][8][4];
            #pragma unroll
            for (int rc = 0; rc < 2; rc++)
                #pragma unroll
                for (int nt = 0; nt < 8; nt++)
                    #pragma unroll
                    for (int e = 0; e < 4; e++) sacc[rc][nt][e] = 0.f;

            #pragma unroll
            for (int ks = 0; ks < 8; ks++) {
                #pragma unroll
                for (int ntp = 0; ntp < 4; ntp++) {
                    uint32_t bb[4];
                    ldsm_x4(bb, kFragBase + (uint32_t)(ntp * 16 * ALD * 4 + ks * 32));
                    mma16n8k8(sacc[0][2 * ntp],     qf[0][ks], bb);
                    mma16n8k8(sacc[1][2 * ntp],     qf[1][ks], bb);
                    mma16n8k8(sacc[0][2 * ntp + 1], qf[0][ks], bb + 2);
                    mma16n8k8(sacc[1][2 * ntp + 1], qf[1][ks], bb + 2);
                }
            }

            // ---- causal mask ----
            if (j0 + 63 > m0 + wrow) {
                #pragma unroll
                for (int rc = 0; rc < 2; rc++)
                    #pragma unroll
                    for (int nt = 0; nt < 8; nt++)
                        #pragma unroll
                        for (int e = 0; e < 4; e++) {
                            const int row = m0 + wrow + 16 * rc + g + (e >> 1) * 8;
                            const int key = j0 + nt * 8 + 2 * tg + (e & 1);
                            if (key > row) sacc[rc][nt][e] = -1e30f;
                        }
            }

            // ---- online softmax (exp2 domain) ----
            #pragma unroll
            for (int rc = 0; rc < 2; rc++) {
                #pragma unroll
                for (int r2 = 0; r2 < 2; r2++) {
                    const int si = rc * 2 + r2;
                    float mx = -1e30f;
                    #pragma unroll
                    for (int nt = 0; nt < 8; nt++)
                        mx = fmaxf(mx, fmaxf(sacc[rc][nt][r2 * 2], sacc[rc][nt][r2 * 2 + 1]));
                    mx = fmaxf(mx, __shfl_xor_sync(0xffffffffu, mx, 1));
                    mx = fmaxf(mx, __shfl_xor_sync(0xffffffffu, mx, 2));
                    const float mn = fmaxf(m_i[si], mx);
                    const float corr = exp2f(m_i[si] - mn);
                    m_i[si] = mn;
                    float rs = 0.f;
                    #pragma unroll
                    for (int nt = 0; nt < 8; nt++) {
                        float p0 = exp2f(sacc[rc][nt][r2 * 2]     - mn);
                        float p1 = exp2f(sacc[rc][nt][r2 * 2 + 1] - mn);
                        sacc[rc][nt][r2 * 2]     = p0;
                        sacc[rc][nt][r2 * 2 + 1] = p1;
                        rs += p0 + p1;
                    }
                    rs += __shfl_xor_sync(0xffffffffu, rs, 1);
                    rs += __shfl_xor_sync(0xffffffffu, rs, 2);
                    l_i[si] = l_i[si] * corr + rs;
                    #pragma unroll
                    for (int nt = 0; nt < 8; nt++) {
                        o[rc][nt][r2 * 2]     *= corr;
                        o[rc][nt][r2 * 2 + 1] *= corr;
                    }
                }
            }

            // ---- stage P into QP (warp-private rows) ----
            {
                float* Ps = QP;
                #pragma unroll
                for (int rc = 0; rc < 2; rc++) {
                    const int rr = wrow + 16 * rc + g;
                    #pragma unroll
                    for (int nt = 0; nt < 8; nt++) {
                        *(float2*)&Ps[rr * ALD + nt * 8 + 2 * tg] =
                            make_float2(rna_tf32(sacc[rc][nt][0]), rna_tf32(sacc[rc][nt][1]));
                        *(float2*)&Ps[(rr + 8) * ALD + nt * 8 + 2 * tg] =
                            make_float2(rna_tf32(sacc[rc][nt][2]), rna_tf32(sacc[rc][nt][3]));
                    }
                }
            }
            __syncwarp();

            // ---- O += P @ V ----
            #pragma unroll
            for (int ks = 0; ks < 8; ks++) {
                const int kk = ks * 8 + tg;
                uint32_t a[2][4];
                ldsm_x4(a[0], pFragBase + (uint32_t)(ks * 32));
                ldsm_x4(a[1], pFragBase + (uint32_t)(16 * ALD * 4 + ks * 32));
                #pragma unroll
                for (int nt = 0; nt < 8; nt++) {
                    uint32_t b[2];
                    b[0] = Vsu[kk * VLD + nt * 8 + g];
                    b[1] = Vsu[(kk + 4) * VLD + nt * 8 + g];
                    mma16n8k8(o[0][nt], a[0], b);
                    mma16n8k8(o[1][nt], a[1], b);
                }
            }
            __syncwarp();
        }

        // ---- normalize, round to tf32 (gemm<1> operand), write g_y ----
        #pragma unroll
        for (int rc = 0; rc < 2; rc++) {
            #pragma unroll
            for (int r2 = 0; r2 < 2; r2++) {
                const float inv = 1.f / l_i[rc * 2 + r2];
                const int row = m0 + wrow + 16 * rc + g + r2 * 8;
                #pragma unroll
                for (int nt = 0; nt < 8; nt++) {
                    float2 v;
                    v.x = rna_tf32(o[rc][nt][r2 * 2]     * inv);
                    v.y = rna_tf32(o[rc][nt][r2 * 2 + 1] * inv);
                    *(float2*)&g_y[((size_t)(b_ * Tv + row)) * Cv + h * 64 + nt * 8 + 2 * tg] = v;
                }
            }
        }
    }
}

// ---------------------------------------------------------------------------
// Output projection GEMM (proven R9 config, MODE 1 only).
// ---------------------------------------------------------------------------
__global__ void __launch_bounds__(256) gemm_out(
    const float* __restrict__ Wt, const float* __restrict__ bias,
    float* __restrict__ out)
{
    extern __shared__ float smg[];
    float* As = smg;
    float* Bs = smg + NSTG * TILEW;

    const int tid  = threadIdx.x;
    const int lane = tid & 31;
    const int wid  = tid >> 5;
    const int wm   = (wid & 1) * 64;
    const int wn   = (wid >> 1) * 32;
    const int g    = lane >> 2;
    const int tg   = lane & 3;

    const int row0 = blockIdx.y * 128;
    const int col0 = blockIdx.x * 128;
    const float* Ab = g_y + (size_t)row0 * Cv;
    const float* Bb = Wt  + (size_t)col0 * Cv;

    const int gr = tid >> 3;
    const int gc = (tid & 7) << 2;

    const uint32_t aBase = (uint32_t)__cvta_generic_to_shared(As);
    const uint32_t bBase = (uint32_t)__cvta_generic_to_shared(Bs);

    const int lrow  = lane & 15;
    const int lcolw = (lane >> 4) << 2;
    const int brow  = (lane & 7) + ((lane & 16) ? 8 : 0);
    const int bcolw = ((lane >> 3) & 1) << 2;
    const uint32_t aFragBase = aBase + (uint32_t)(((wm + lrow) * LDW + lcolw) * 4);
    const uint32_t bFragBase = bBase + (uint32_t)(((wn + brow) * LDW + bcolw) * 4);

    float c[4][4][4];
    #pragma unroll
    for (int mt = 0; mt < 4; mt++)
        #pragma unroll
        for (int nt = 0; nt < 4; nt++)
            #pragma unroll
            for (int i = 0; i < 4; i++) c[mt][nt][i] = 0.f;

    const int NC = Cv / BK;   // 32

    auto issue = [&](int ch) {
        if (ch < NC) {
            const int s = ch % NSTG;
            const float* gA = Ab + ch * BK;
            const float* gB = Bb + ch * BK;
            const uint32_t ab = aBase + (uint32_t)(s * TILEW * 4);
            const uint32_t bb = bBase + (uint32_t)(s * TILEW * 4);
            #pragma unroll
            for (int i = 0; i < 4; i++) {
                const int r = gr + i * 32;
                const uint32_t off = (uint32_t)((r * LDW + gc) * 4);
                cp_async16(ab + off, gA + (size_t)r * Cv + gc);
                cp_async16(bb + off, gB + (size_t)r * Cv + gc);
            }
        }
        asm volatile("cp.async.commit_group;" ::: "memory");
    };

    issue(0);
    issue(1);

    for (int ch = 0; ch < NC; ch++) {
        asm volatile("cp.async.wait_group 1;" ::: "memory");
        __syncthreads();
        issue(ch + 2);

        const int s = ch % NSTG;
        const uint32_t aStage = aFragBase + (uint32_t)(s * TILEW * 4);
        const uint32_t bStage = bFragBase + (uint32_t)(s * TILEW * 4);

        #pragma unroll
        for (int ks = 0; ks < 4; ks++) {
            uint32_t a[4][4];
            #pragma unroll
            for (int mt = 0; mt < 4; mt++)
                ldsm_x4(a[mt], aStage + (uint32_t)(mt * 16 * LDW * 4 + ks * 32));
            uint32_t b[2][4];
            #pragma unroll
            for (int ntp = 0; ntp < 2; ntp++)
                ldsm_x4(b[ntp], bStage + (uint32_t)(ntp * 16 * LDW * 4 + ks * 32));
            #pragma unroll
            for (int mt = 0; mt < 4; mt++)
                #pragma unroll
                for (int nt = 0; nt < 4; nt++)
                    mma16n8k8(c[mt][nt], a[mt], b[nt >> 1] + (nt & 1) * 2);
        }
    }

    #pragma unroll
    for (int mt = 0; mt < 4; mt++) {
        #pragma unroll
        for (int r2 = 0; r2 < 2; r2++) {
            const int row = row0 + wm + mt * 16 + g + r2 * 8;
            #pragma unroll
            for (int nt = 0; nt < 4; nt++) {
                const int col = col0 + wn + nt * 8 + tg * 2;
                float2 v;
                v.x = c[mt][nt][r2 * 2 + 0] + __ldg(bias + col + 0);
                v.y = c[mt][nt][r2 * 2 + 1] + __ldg(bias + col + 1);
                *(float2*)&out[(size_t)row * Cv + col] = v;
            }
        }
    }
}

// ---------------------------------------------------------------------------
extern "C" void kernel_launch(void* const* d_in, const int* in_sizes, int n_in,
                              void* d_out, int out_size)
{
    const float* x     = (const float*)d_in[0];
    const float* W_qkv = (const float*)d_in[1];
    const float* b_qkv = (const float*)d_in[2];
    const float* W_out = (const float*)d_in[3];
    const float* b_out = (const float*)d_in[4];
    float* out = (float*)d_out;

    float* xr;  cudaGetSymbolAddress((void**)&xr,  g_xr);
    float* wqT; cudaGetSymbolAddress((void**)&wqT, g_wqT);
    float* woT; cudaGetSymbolAddress((void**)&woT, g_woT);

    cudaFuncSetAttribute(fused_kernel,
                         cudaFuncAttributeMaxDynamicSharedMemorySize, FUSED_SMEM);
    cudaFuncSetAttribute(gemm_out,
                         cudaFuncAttributeMaxDynamicSharedMemorySize, GEMM_SMEM);

    // prep: reset scheduler state; round x; transpose+round weights
    zero_sched_kernel<<<7, 256>>>();
    round_rna_kernel<<<2048, 256>>>((const float4*)x, (float4*)xr, Mrows * Cv / 4);
    transpose_rna_kernel<<<dim3(3 * Cv / 32, Cv / 32), dim3(32, 8)>>>(W_qkv, wqT, Cv, 3 * Cv);
    transpose_rna_kernel<<<dim3(Cv / 32, Cv / 32), dim3(32, 8)>>>(W_out, woT, Cv, Cv);

    // 1+2) fused persistent QKV projection + causal flash attention
    fused_kernel<<<NSLOTS, 256, FUSED_SMEM>>>(xr, wqT, b_qkv);

    // 3) output projection
    gemm_out<<<dim3(Cv / 128, Mrows / 128), 256, GEMM_SMEM>>>(woT, b_out, out);
}

// round 16
// speedup vs baseline: 1.1380x; 1.1380x over previous
#include <cuda_runtime.h>
#include <math.h>
#include <stdint.h>

#define Bv 4
#define Tv 2048
#define Cv 1024
#define Hv 16
#define Dv 64
#define Mrows (Bv*Tv)   // 8192

// ---------------- scratch (device globals; allocation-free) ----------------
__device__ float g_q[Bv*Hv*Tv*Dv];    // [B,H,T,D] (tf32-rounded)
__device__ float g_k[Bv*Hv*Tv*Dv];
__device__ float g_v[Bv*Hv*Tv*Dv];
__device__ float g_y[Bv*Tv*Cv];       // attention output [B,T,C] (tf32-rounded)
__device__ float g_xr[Mrows*Cv];      // x, tf32-rounded
__device__ float g_wqT[3*Cv*Cv];      // W_qkv^T, tf32-rounded
__device__ float g_woT[Cv*Cv];        // W_out^T, tf32-rounded
__device__ int   g_flag[1536];        // per-gemm-tile done flags (bx*64+by)
__device__ int   g_qhead;             // gemm tile queue
__device__ int   g_ahead;             // attention job queue

__device__ __forceinline__ float rna_tf32(float x) {
    uint32_t u;
    asm("cvt.rna.tf32.f32 %0, %1;" : "=r"(u) : "f"(x));
    return __uint_as_float(u);
}

__device__ __forceinline__ void mma16n8k8(float* c, const uint32_t* a, const uint32_t* b) {
    asm volatile(
        "mma.sync.aligned.m16n8k8.row.col.f32.tf32.tf32.f32 "
        "{%0,%1,%2,%3}, {%4,%5,%6,%7}, {%8,%9}, {%0,%1,%2,%3};"
        : "+f"(c[0]), "+f"(c[1]), "+f"(c[2]), "+f"(c[3])
        : "r"(a[0]), "r"(a[1]), "r"(a[2]), "r"(a[3]), "r"(b[0]), "r"(b[1]));
}

__device__ __forceinline__ void ldsm_x4(uint32_t* r, uint32_t addr) {
    asm volatile(
        "ldmatrix.sync.aligned.m8n8.x4.shared.b16 {%0,%1,%2,%3}, [%4];"
        : "=r"(r[0]), "=r"(r[1]), "=r"(r[2]), "=r"(r[3]) : "r"(addr));
}

__device__ __forceinline__ void cp_async16(uint32_t dst, const float* src) {
    asm volatile("cp.async.cg.shared.global [%0], [%1], 16;" :: "r"(dst), "l"(src) : "memory");
}

__device__ __forceinline__ void wait_flag(const int* f) {
    if ((threadIdx.x & 31) == 0) {
        int v;
        do {
            asm volatile("ld.acquire.gpu.b32 %0, [%1];" : "=r"(v) : "l"(f) : "memory");
            if (!v) __nanosleep(200);
        } while (!v);
    }
    __syncwarp();
}

// gemm tile queue order: [q mt=15][kv mt'=0][q 14][kv 1] ... (96 per super-block)
__device__ __forceinline__ void sched_tile(int t, int& bx, int& by) {
    const int j = t / 96, r = t - j * 96;
    if (r < 32) { bx = r & 7;             by = (r >> 3) * 16 + (15 - j); }
    else        { const int i2 = r - 32;  bx = 8 + (i2 & 15); by = (i2 >> 4) * 16 + j; }
}

// ---------------- prep kernels ----------------
__global__ void zero_sched_kernel() {
    const int i = blockIdx.x * blockDim.x + threadIdx.x;
    if (i < 1536) g_flag[i] = 0;
    if (i == 1536) g_qhead = 0;
    if (i == 1537) g_ahead = 0;
}
__global__ void round_rna_kernel(const float4* __restrict__ src, float4* __restrict__ dst, int n4) {
    for (int i = blockIdx.x * blockDim.x + threadIdx.x; i < n4; i += gridDim.x * blockDim.x) {
        float4 v = src[i];
        v.x = rna_tf32(v.x); v.y = rna_tf32(v.y);
        v.z = rna_tf32(v.z); v.w = rna_tf32(v.w);
        dst[i] = v;
    }
}
__global__ void transpose_rna_kernel(const float* __restrict__ src, float* __restrict__ dst,
                                     int K, int N) {
    __shared__ float t[32][33];
    int n0 = blockIdx.x * 32, k0 = blockIdx.y * 32;
    #pragma unroll
    for (int i = 0; i < 32; i += 8)
        t[threadIdx.y + i][threadIdx.x] =
            src[(size_t)(k0 + threadIdx.y + i) * N + n0 + threadIdx.x];
    __syncthreads();
    #pragma unroll
    for (int i = 0; i < 32; i += 8)
        dst[(size_t)(n0 + threadIdx.y + i) * K + k0 + threadIdx.x] =
            rna_tf32(t[threadIdx.x][threadIdx.y + i]);
}

// ---------------- tile geometry ----------------
#define BK 32
#define LDW 36
#define NSTG 3
#define TILEW (128*LDW)
#define GEMM_SMEM (NSTG * 2 * TILEW * 4)      // 110592 B

#define ALD 68
#define VLD 72
#define KVSTG (64*ALD + 64*VLD)
#define FUSED_SMEM GEMM_SMEM
#define NSLOTS 296

// ---------------------------------------------------------------------------
// FUSED persistent kernel.
// Phase 1: QKV gemm tiles (atomic queue, 8 warps, 114 regs).
// Phase 2: attention jobs on ALL 8 warps x 16 q-rows (~95 regs, fits the
//          (256,2) cap without spilling — the R15 failure mode).
// ---------------------------------------------------------------------------
__global__ void __launch_bounds__(256, 2) fused_kernel(
    const float* __restrict__ xr, const float* __restrict__ wqT,
    const float* __restrict__ b_qkv)
{
    extern __shared__ float smg[];
    __shared__ int s_work;

    const int tid  = threadIdx.x;
    const int lane = tid & 31;
    const int g    = lane >> 2;
    const int tg   = lane & 3;

    const int lrow  = lane & 15;
    const int lcolw = (lane >> 4) << 2;
    const int brow  = (lane & 7) + ((lane & 16) ? 8 : 0);
    const int bcolw = ((lane >> 3) & 1) << 2;

    // ============== PHASE 1: gemm<0> tiles ==============
    {
        float* As = smg;
        float* Bs = smg + NSTG * TILEW;

        const int wid = tid >> 5;
        const int wm  = (wid & 1) * 64;
        const int wn  = (wid >> 1) * 32;
        const int gr  = tid >> 3;
        const int gc  = (tid & 7) << 2;

        const uint32_t aBase = (uint32_t)__cvta_generic_to_shared(As);
        const uint32_t bBase = (uint32_t)__cvta_generic_to_shared(Bs);
        const uint32_t aFragBase = aBase + (uint32_t)(((wm + lrow) * LDW + lcolw) * 4);
        const uint32_t bFragBase = bBase + (uint32_t)(((wn + brow) * LDW + bcolw) * 4);

        const int NC = Cv / BK;   // 32

        for (;;) {
            __syncthreads();
            if (tid == 0) s_work = atomicAdd(&g_qhead, 1);
            __syncthreads();
            const int t = s_work;
            if (t >= 1536) break;

            int bx, by;
            sched_tile(t, bx, by);
            const int row0 = by * 128;
            const int col0 = bx * 128;
            const float* Ab = xr  + (size_t)row0 * Cv;
            const float* Bb = wqT + (size_t)col0 * Cv;

            float c[4][4][4];
            #pragma unroll
            for (int mt = 0; mt < 4; mt++)
                #pragma unroll
                for (int nt = 0; nt < 4; nt++)
                    #pragma unroll
                    for (int i = 0; i < 4; i++) c[mt][nt][i] = 0.f;

            auto issue = [&](int ch) {
                if (ch < NC) {
                    const int s = ch % NSTG;
                    const float* gA = Ab + ch * BK;
                    const float* gB = Bb + ch * BK;
                    const uint32_t ab = aBase + (uint32_t)(s * TILEW * 4);
                    const uint32_t bb = bBase + (uint32_t)(s * TILEW * 4);
                    #pragma unroll
                    for (int i = 0; i < 4; i++) {
                        const int r = gr + i * 32;
                        const uint32_t off = (uint32_t)((r * LDW + gc) * 4);
                        cp_async16(ab + off, gA + (size_t)r * Cv + gc);
                        cp_async16(bb + off, gB + (size_t)r * Cv + gc);
                    }
                }
                asm volatile("cp.async.commit_group;" ::: "memory");
            };

            issue(0);
            issue(1);

            for (int ch = 0; ch < NC; ch++) {
                asm volatile("cp.async.wait_group 1;" ::: "memory");
                __syncthreads();
                issue(ch + 2);

                const int s = ch % NSTG;
                const uint32_t aStage = aFragBase + (uint32_t)(s * TILEW * 4);
                const uint32_t bStage = bFragBase + (uint32_t)(s * TILEW * 4);

                #pragma unroll
                for (int ks = 0; ks < 4; ks++) {
                    uint32_t a[4][4];
                    #pragma unroll
                    for (int mt = 0; mt < 4; mt++)
                        ldsm_x4(a[mt], aStage + (uint32_t)(mt * 16 * LDW * 4 + ks * 32));
                    uint32_t b[2][4];
                    #pragma unroll
                    for (int ntp = 0; ntp < 2; ntp++)
                        ldsm_x4(b[ntp], bStage + (uint32_t)(ntp * 16 * LDW * 4 + ks * 32));
                    #pragma unroll
                    for (int mt = 0; mt < 4; mt++)
                        #pragma unroll
                        for (int nt = 0; nt < 4; nt++)
                            mma16n8k8(c[mt][nt], a[mt], b[nt >> 1] + (nt & 1) * 2);
                }
            }

            #pragma unroll
            for (int mt = 0; mt < 4; mt++) {
                #pragma unroll
                for (int r2 = 0; r2 < 2; r2++) {
                    const int row = row0 + wm + mt * 16 + g + r2 * 8;
                    const int b_ = row >> 11, t_ = row & 2047;
                    #pragma unroll
                    for (int nt = 0; nt < 4; nt++) {
                        const int col = col0 + wn + nt * 8 + tg * 2;
                        float2 v;
                        v.x = rna_tf32(c[mt][nt][r2 * 2 + 0] + __ldg(b_qkv + col + 0));
                        v.y = rna_tf32(c[mt][nt][r2 * 2 + 1] + __ldg(b_qkv + col + 1));
                        const int which = col >> 10;
                        const int cc = col & 1023;
                        const int h = cc >> 6, d = cc & 63;
                        float* dst = (which == 0) ? g_q : (which == 1) ? g_k : g_v;
                        *(float2*)&dst[((size_t)((b_ * Hv + h) * Tv + t_)) * Dv + d] = v;
                    }
                }
            }

            __threadfence();
            __syncthreads();
            if (tid == 0)
                asm volatile("st.release.gpu.b32 [%0], %1;"
                             :: "l"(g_flag + bx * 64 + by), "r"(1) : "memory");
        }
    }

    // ============== PHASE 2: attention (8 warps x 16 q-rows) ==============
    float* QP = smg;                   // [128][68]: Q then P staging
    float* KV = smg + 128 * ALD;

    const uint32_t qpBase = (uint32_t)__cvta_generic_to_shared(QP);
    const uint32_t kvBase = (uint32_t)__cvta_generic_to_shared(KV);

    const int w = tid >> 5;            // 0..7
    const int wrow = 16 * w;
    const uint32_t pFragBase = qpBase + (uint32_t)(((wrow + lrow) * ALD + lcolw) * 4);

    const float QSCALE = 0.125f * 1.4426950408889634f;   // log2(e)/8

    for (;;) {
        __syncthreads();                 // QP/s_work reuse guard
        if (tid == 0) s_work = atomicAdd(&g_ahead, 1);
        __syncthreads();
        const int p = s_work;
        if (p >= 1024) return;

        const int m0 = (15 - (p >> 6)) * 128;   // heavy jobs first
        const int bh = p & 63;
        const int b_ = bh >> 4;
        const int h  = bh & 15;
        const int h2 = h >> 1;
        const int mt = m0 >> 7;

        const float* qp = g_q + (size_t)bh * Tv * Dv;
        const float* kp = g_k + (size_t)bh * Tv * Dv;
        const float* vp = g_v + (size_t)bh * Tv * Dv;

        auto issue_kv = [&](int kt) {
            const int s = kt & 1;
            const float* kpt = kp + (size_t)(kt * 64) * Dv;
            const float* vpt = vp + (size_t)(kt * 64) * Dv;
            const uint32_t kb = kvBase + (uint32_t)(s * KVSTG * 4);
            const uint32_t vb = kb + (uint32_t)(64 * ALD * 4);
            #pragma unroll
            for (int i = 0; i < 4; i++) {
                const int f = i * 256 + tid;
                const int rr = f >> 4, c4 = (f & 15) << 2;
                cp_async16(kb + (uint32_t)((rr * ALD + c4) * 4), kpt + rr * Dv + c4);
                cp_async16(vb + (uint32_t)((rr * VLD + c4) * 4), vpt + rr * Dv + c4);
            }
            asm volatile("cp.async.commit_group;" ::: "memory");
        };

        // producer gates: q tile + kv row-block 0
        wait_flag(g_flag + h2 * 64 + b_ * 16 + mt);
        wait_flag(g_flag + (8 + h2) * 64 + b_ * 16);
        wait_flag(g_flag + (16 + h2) * 64 + b_ * 16);

        issue_kv(0);

        // Load Q tile, scale by log2(e)/8, re-round to tf32.
        #pragma unroll
        for (int i = 0; i < 8; i++) {
            const int f = i * 256 + tid;
            const int rr = f >> 4, c4 = (f & 15) << 2;
            float4 v = *(const float4*)(qp + (size_t)(m0 + rr) * Dv + c4);
            v.x = rna_tf32(v.x * QSCALE);
            v.y = rna_tf32(v.y * QSCALE);
            v.z = rna_tf32(v.z * QSCALE);
            v.w = rna_tf32(v.w * QSCALE);
            *(float4*)&QP[rr * ALD + c4] = v;
        }
        __syncthreads();

        // Hoist Q fragments (32 regs); QP becomes P staging afterwards.
        uint32_t qf[8][4];
        #pragma unroll
        for (int ks = 0; ks < 8; ks++)
            ldsm_x4(qf[ks], pFragBase + (uint32_t)(ks * 32));

        float m_i[2] = {-1e30f, -1e30f};
        float l_i[2] = {0.f, 0.f};
        float o[8][4];
        #pragma unroll
        for (int nt = 0; nt < 8; nt++)
            #pragma unroll
            for (int e = 0; e < 4; e++) o[nt][e] = 0.f;

        const int nkt = m0 / 64 + 2;
        for (int kt = 0; kt < nkt; kt++) {
            const int j0 = kt * 64;
            asm volatile("cp.async.wait_group 0;" ::: "memory");
            __syncthreads();
            if (kt + 1 < nkt) {
                if (((kt + 1) & 1) == 0) {
                    const int rb = (kt + 1) >> 1;
                    wait_flag(g_flag + (8 + h2) * 64 + b_ * 16 + rb);
                    wait_flag(g_flag + (16 + h2) * 64 + b_ * 16 + rb);
                }
                issue_kv(kt + 1);
            }

            const int s = kt & 1;
            const uint32_t kFragBase = kvBase + (uint32_t)(s * KVSTG * 4)
                                     + (uint32_t)((brow * ALD + bcolw) * 4);
            const uint32_t* Vsu = (const uint32_t*)(KV + s * KVSTG + 64 * ALD);

            // ---- S = Q @ K^T (log2 domain) ----
            float sacc[8][4];
            #pragma unroll
            for (int nt = 0; nt < 8; nt++)
                #pragma unroll
                for (int e = 0; e < 4; e++) sacc[nt][e] = 0.f;

            #pragma unroll
            for (int ks = 0; ks < 8; ks++) {
                #pragma unroll
                for (int ntp = 0; ntp < 4; ntp++) {
                    uint32_t bb[4];
                    ldsm_x4(bb, kFragBase + (uint32_t)(ntp * 16 * ALD * 4 + ks * 32));
                    mma16n8k8(sacc[2 * ntp],     qf[ks], bb);
                    mma16n8k8(sacc[2 * ntp + 1], qf[ks], bb + 2);
                }
            }

            // ---- causal mask ----
            if (j0 + 63 > m0 + wrow) {
                #pragma unroll
                for (int nt = 0; nt < 8; nt++)
                    #pragma unroll
                    for (int e = 0; e < 4; e++) {
                        const int row = m0 + wrow + g + (e >> 1) * 8;
                        const int key = j0 + nt * 8 + 2 * tg + (e & 1);
                        if (key > row) sacc[nt][e] = -1e30f;
                    }
            }

            // ---- online softmax (exp2 domain) ----
            #pragma unroll
            for (int r2 = 0; r2 < 2; r2++) {
                float mx = -1e30f;
                #pragma unroll
                for (int nt = 0; nt < 8; nt++)
                    mx = fmaxf(mx, fmaxf(sacc[nt][r2 * 2], sacc[nt][r2 * 2 + 1]));
                mx = fmaxf(mx, __shfl_xor_sync(0xffffffffu, mx, 1));
                mx = fmaxf(mx, __shfl_xor_sync(0xffffffffu, mx, 2));
                const float mn = fmaxf(m_i[r2], mx);
                const float corr = exp2f(m_i[r2] - mn);
                m_i[r2] = mn;
                float rs = 0.f;
                #pragma unroll
                for (int nt = 0; nt < 8; nt++) {
                    float p0 = exp2f(sacc[nt][r2 * 2]     - mn);
                    float p1 = exp2f(sacc[nt][r2 * 2 + 1] - mn);
                    sacc[nt][r2 * 2]     = p0;
                    sacc[nt][r2 * 2 + 1] = p1;
                    rs += p0 + p1;
                }
                rs += __shfl_xor_sync(0xffffffffu, rs, 1);
                rs += __shfl_xor_sync(0xffffffffu, rs, 2);
                l_i[r2] = l_i[r2] * corr + rs;
                #pragma unroll
                for (int nt = 0; nt < 8; nt++) {
                    o[nt][r2 * 2]     *= corr;
                    o[nt][r2 * 2 + 1] *= corr;
                }
            }

            // ---- stage P into QP (rows wrow..wrow+15, warp-private) ----
            {
                float* Ps = QP;
                const int rr = wrow + g;
                #pragma unroll
                for (int nt = 0; nt < 8; nt++) {
                    *(float2*)&Ps[rr * ALD + nt * 8 + 2 * tg] =
                        make_float2(rna_tf32(sacc[nt][0]), rna_tf32(sacc[nt][1]));
                    *(float2*)&Ps[(rr + 8) * ALD + nt * 8 + 2 * tg] =
                        make_float2(rna_tf32(sacc[nt][2]), rna_tf32(sacc[nt][3]));
                }
            }
            __syncwarp();

            // ---- O += P @ V ----
            #pragma unroll
            for (int ks = 0; ks < 8; ks++) {
                const int kk = ks * 8 + tg;
                uint32_t a[4];
                ldsm_x4(a, pFragBase + (uint32_t)(ks * 32));
                #pragma unroll
                for (int nt = 0; nt < 8; nt++) {
                    uint32_t b[2];
                    b[0] = Vsu[kk * VLD + nt * 8 + g];
                    b[1] = Vsu[(kk + 4) * VLD + nt * 8 + g];
                    mma16n8k8(o[nt], a, b);
                }
            }
            __syncwarp();
        }

        // ---- normalize, round to tf32 (gemm_out operand), write g_y ----
        #pragma unroll
        for (int r2 = 0; r2 < 2; r2++) {
            const float inv = 1.f / l_i[r2];
            const int row = m0 + wrow + g + r2 * 8;
            #pragma unroll
            for (int nt = 0; nt < 8; nt++) {
                float2 v;
                v.x = rna_tf32(o[nt][r2 * 2]     * inv);
                v.y = rna_tf32(o[nt][r2 * 2 + 1] * inv);
                *(float2*)&g_y[((size_t)(b_ * Tv + row)) * Cv + h * 64 + nt * 8 + 2 * tg] = v;
            }
        }
    }
}

// ---------------------------------------------------------------------------
// Output projection GEMM (proven R9 config).
// ---------------------------------------------------------------------------
__global__ void __launch_bounds__(256) gemm_out(
    const float* __restrict__ Wt, const float* __restrict__ bias,
    float* __restrict__ out)
{
    extern __shared__ float smg[];
    float* As = smg;
    float* Bs = smg + NSTG * TILEW;

    const int tid  = threadIdx.x;
    const int lane = tid & 31;
    const int wid  = tid >> 5;
    const int wm   = (wid & 1) * 64;
    const int wn   = (wid >> 1) * 32;
    const int g    = lane >> 2;
    const int tg   = lane & 3;

    const int row0 = blockIdx.y * 128;
    const int col0 = blockIdx.x * 128;
    const float* Ab = g_y + (size_t)row0 * Cv;
    const float* Bb = Wt  + (size_t)col0 * Cv;

    const int gr = tid >> 3;
    const int gc = (tid & 7) << 2;

    const uint32_t aBase = (uint32_t)__cvta_generic_to_shared(As);
    const uint32_t bBase = (uint32_t)__cvta_generic_to_shared(Bs);

    const int lrow  = lane & 15;
    const int lcolw = (lane >> 4) << 2;
    const int brow  = (lane & 7) + ((lane & 16) ? 8 : 0);
    const int bcolw = ((lane >> 3) & 1) << 2;
    const uint32_t aFragBase = aBase + (uint32_t)(((wm + lrow) * LDW + lcolw) * 4);
    const uint32_t bFragBase = bBase + (uint32_t)(((wn + brow) * LDW + bcolw) * 4);

    float c[4][4][4];
    #pragma unroll
    for (int mt = 0; mt < 4; mt++)
        #pragma unroll
        for (int nt = 0; nt < 4; nt++)
            #pragma unroll
            for (int i = 0; i < 4; i++) c[mt][nt][i] = 0.f;

    const int NC = Cv / BK;   // 32

    auto issue = [&](int ch) {
        if (ch < NC) {
            const int s = ch % NSTG;
            const float* gA = Ab + ch * BK;
            const float* gB = Bb + ch * BK;
            const uint32_t ab = aBase + (uint32_t)(s * TILEW * 4);
            const uint32_t bb = bBase + (uint32_t)(s * TILEW * 4);
            #pragma unroll
            for (int i = 0; i < 4; i++) {
                const int r = gr + i * 32;
                const uint32_t off = (uint32_t)((r * LDW + gc) * 4);
                cp_async16(ab + off, gA + (size_t)r * Cv + gc);
                cp_async16(bb + off, gB + (size_t)r * Cv + gc);
            }
        }
        asm volatile("cp.async.commit_group;" ::: "memory");
    };

    issue(0);
    issue(1);

    for (int ch = 0; ch < NC; ch++) {
        asm volatile("cp.async.wait_group 1;" ::: "memory");
        __syncthreads();
        issue(ch + 2);

        const int s = ch % NSTG;
        const uint32_t aStage = aFragBase + (uint32_t)(s * TILEW * 4);
        const uint32_t bStage = bFragBase + (uint32_t)(s * TILEW * 4);

        #pragma unroll
        for (int ks = 0; ks < 4; ks++) {
            uint32_t a[4][4];
            #pragma unroll
            for (int mt = 0; mt < 4; mt++)
                ldsm_x4(a[mt], aStage + (uint32_t)(mt * 16 * LDW * 4 + ks * 32));
            uint32_t b[2][4];
            #pragma unroll
            for (int ntp = 0; ntp < 2; ntp++)
                ldsm_x4(b[ntp], bStage + (uint32_t)(ntp * 16 * LDW * 4 + ks * 32));
            #pragma unroll
            for (int mt = 0; mt < 4; mt++)
                #pragma unroll
                for (int nt = 0; nt < 4; nt++)
                    mma16n8k8(c[mt][nt], a[mt], b[nt >> 1] + (nt & 1) * 2);
        }
    }

    #pragma unroll
    for (int mt = 0; mt < 4; mt++) {
        #pragma unroll
        for (int r2 = 0; r2 < 2; r2++) {
            const int row = row0 + wm + mt * 16 + g + r2 * 8;
            #pragma unroll
            for (int nt = 0; nt < 4; nt++) {
                const int col = col0 + wn + nt * 8 + tg * 2;
                float2 v;
                v.x = c[mt][nt][r2 * 2 + 0] + __ldg(bias + col + 0);
                v.y = c[mt][nt][r2 * 2 + 1] + __ldg(bias + col + 1);
                *(float2*)&out[(size_t)row * Cv + col] = v;
            }
        }
    }
}

// ---------------------------------------------------------------------------
extern "C" void kernel_launch(void* const* d_in, const int* in_sizes, int n_in,
                              void* d_out, int out_size)
{
    const float* x     = (const float*)d_in[0];
    const float* W_qkv = (const float*)d_in[1];
    const float* b_qkv = (const float*)d_in[2];
    const float* W_out = (const float*)d_in[3];
    const float* b_out = (const float*)d_in[4];
    float* out = (float*)d_out;

    float* xr;  cudaGetSymbolAddress((void**)&xr,  g_xr);
    float* wqT; cudaGetSymbolAddress((void**)&wqT, g_wqT);
    float* woT; cudaGetSymbolAddress((void**)&woT, g_woT);

    cudaFuncSetAttribute(fused_kernel,
                         cudaFuncAttributeMaxDynamicSharedMemorySize, FUSED_SMEM);
    cudaFuncSetAttribute(gemm_out,
                         cudaFuncAttributeMaxDynamicSharedMemorySize, GEMM_SMEM);

    // prep: reset scheduler state; round x; transpose+round weights
    zero_sched_kernel<<<7, 256>>>();
    round_rna_kernel<<<2048, 256>>>((const float4*)x, (float4*)xr, Mrows * Cv / 4);
    transpose_rna_kernel<<<dim3(3 * Cv / 32, Cv / 32), dim3(32, 8)>>>(W_qkv, wqT, Cv, 3 * Cv);
    transpose_rna_kernel<<<dim3(Cv / 32, Cv / 32), dim3(32, 8)>>>(W_out, woT, Cv, Cv);

    // 1+2) fused persistent QKV projection + causal flash attention
    fused_kernel<<<NSLOTS, 256, FUSED_SMEM>>>(xr, wqT, b_qkv);

    // 3) output projection
    gemm_out<<<dim3(Cv / 128, Mrows / 128), 256, GEMM_SMEM>>>(woT, b_out, out);
}

// round 17
// speedup vs baseline: 1.2188x; 1.0710x over previous
#include <cuda_runtime.h>
#include <math.h>
#include <stdint.h>

#define Bv 4
#define Tv 2048
#define Cv 1024
#define Hv 16
#define Dv 64
#define Mrows (Bv*Tv)   // 8192

// ---------------- scratch (device globals; allocation-free) ----------------
__device__ float g_q[Bv*Hv*Tv*Dv];    // [B,H,T,D] (tf32-rounded)
__device__ float g_k[Bv*Hv*Tv*Dv];    // [B,H,T,D]
__device__ float g_v[Bv*Hv*Tv*Dv];    // [B,H,T,D]
__device__ float g_y[Bv*Tv*Cv];       // attention output [B,T,C] (tf32-rounded)
__device__ float g_xr[Mrows*Cv];      // x, tf32-rounded
__device__ float g_wqT[3*Cv*Cv];      // W_qkv^T [3072][1024], tf32-rounded
__device__ float g_woT[Cv*Cv];        // W_out^T [1024][1024], tf32-rounded

__device__ __forceinline__ float rna_tf32(float x) {
    uint32_t u;
    asm("cvt.rna.tf32.f32 %0, %1;" : "=r"(u) : "f"(x));
    return __uint_as_float(u);
}

__device__ __forceinline__ void mma16n8k8(float* c, const uint32_t* a, const uint32_t* b) {
    asm volatile(
        "mma.sync.aligned.m16n8k8.row.col.f32.tf32.tf32.f32 "
        "{%0,%1,%2,%3}, {%4,%5,%6,%7}, {%8,%9}, {%0,%1,%2,%3};"
        : "+f"(c[0]), "+f"(c[1]), "+f"(c[2]), "+f"(c[3])
        : "r"(a[0]), "r"(a[1]), "r"(a[2]), "r"(a[3]), "r"(b[0]), "r"(b[1]));
}

__device__ __forceinline__ void ldsm_x4(uint32_t* r, uint32_t addr) {
    asm volatile(
        "ldmatrix.sync.aligned.m8n8.x4.shared.b16 {%0,%1,%2,%3}, [%4];"
        : "=r"(r[0]), "=r"(r[1]), "=r"(r[2]), "=r"(r[3]) : "r"(addr));
}

__device__ __forceinline__ void cp_async16(uint32_t dst, const float* src) {
    asm volatile("cp.async.cg.shared.global [%0], [%1], 16;" :: "r"(dst), "l"(src) : "memory");
}

// ---------------------------------------------------------------------------
// Unified prep kernel (single launch):
//   blocks [0, 1024)        : round x -> g_xr            (stride loop, float4)
//   blocks [1024, 4096)     : transpose+round W_qkv -> g_wqT  (32x32 tiles)
//   blocks [4096, 5120)     : transpose+round W_out -> g_woT
// 256 threads; transpose blocks use tid as (tx = tid&31, ty = tid>>5).
// ---------------------------------------------------------------------------
__global__ void __launch_bounds__(256) prep_kernel(
    const float* __restrict__ x, const float* __restrict__ W_qkv,
    const float* __restrict__ W_out)
{
    const int bid = blockIdx.x;
    const int tid = threadIdx.x;

    if (bid < 1024) {
        // round x: 8192*1024 floats = 2M float4
        const float4* src = (const float4*)x;
        float4* dst;
        {
            float* p = g_xr;
            dst = (float4*)p;
        }
        const int n4 = Mrows * Cv / 4;
        for (int i = bid * 256 + tid; i < n4; i += 1024 * 256) {
            float4 v = src[i];
            v.x = rna_tf32(v.x); v.y = rna_tf32(v.y);
            v.z = rna_tf32(v.z); v.w = rna_tf32(v.w);
            dst[i] = v;
        }
        return;
    }

    __shared__ float t[32][33];
    const int tx = tid & 31;
    const int ty = tid >> 5;

    const float* src;
    float* dst;
    int K, N, tb;
    if (bid < 4096) {            // W_qkv [1024][3072] -> g_wqT [3072][1024]
        src = W_qkv; dst = g_wqT; K = Cv; N = 3 * Cv; tb = bid - 1024;
    } else {                     // W_out [1024][1024] -> g_woT [1024][1024]
        src = W_out; dst = g_woT; K = Cv; N = Cv;     tb = bid - 4096;
    }
    const int ntx = N / 32;      // tiles along N
    const int n0 = (tb % ntx) * 32;
    const int k0 = (tb / ntx) * 32;

    #pragma unroll
    for (int i = 0; i < 32; i += 8)
        t[ty + i][tx] = src[(size_t)(k0 + ty + i) * N + n0 + tx];
    __syncthreads();
    #pragma unroll
    for (int i = 0; i < 32; i += 8)
        dst[(size_t)(n0 + ty + i) * K + k0 + tx] = rna_tf32(t[tx][ty + i]);
}

// ---------------------------------------------------------------------------
// tf32 warp-MMA GEMM — proven R9/R14 configuration (unchanged):
// 3-stage cp.async, single barrier per chunk, full ldmatrix, 2 CTAs/SM.
// ---------------------------------------------------------------------------
#define BK 32
#define LDW 36
#define NSTG 3
#define TILEW (128*LDW)
#define GEMM_SMEM (NSTG * 2 * TILEW * 4)      // 110592 B

template<int MODE>
__global__ void __launch_bounds__(256) gemm_mma(
    const float* __restrict__ A_in, const float* __restrict__ Wt,
    const float* __restrict__ bias, float* __restrict__ out)
{
    extern __shared__ float smg[];
    float* As = smg;
    float* Bs = smg + NSTG * TILEW;

    const float* A = (MODE == 1) ? g_y : A_in;

    const int tid  = threadIdx.x;
    const int lane = tid & 31;
    const int wid  = tid >> 5;
    const int wm   = (wid & 1) * 64;
    const int wn   = (wid >> 1) * 32;
    const int g    = lane >> 2;
    const int tg   = lane & 3;

    const int row0 = blockIdx.y * 128;
    const int col0 = blockIdx.x * 128;
    const float* Ab = A  + (size_t)row0 * Cv;
    const float* Bb = Wt + (size_t)col0 * Cv;

    const int gr = tid >> 3;
    const int gc = (tid & 7) << 2;

    const uint32_t aBase = (uint32_t)__cvta_generic_to_shared(As);
    const uint32_t bBase = (uint32_t)__cvta_generic_to_shared(Bs);

    const int lrow  = lane & 15;
    const int lcolw = (lane >> 4) << 2;
    const int brow  = (lane & 7) + ((lane & 16) ? 8 : 0);
    const int bcolw = ((lane >> 3) & 1) << 2;
    const uint32_t aFragBase = aBase + (uint32_t)(((wm + lrow) * LDW + lcolw) * 4);
    const uint32_t bFragBase = bBase + (uint32_t)(((wn + brow) * LDW + bcolw) * 4);

    float c[4][4][4];
    #pragma unroll
    for (int mt = 0; mt < 4; mt++)
        #pragma unroll
        for (int nt = 0; nt < 4; nt++)
            #pragma unroll
            for (int i = 0; i < 4; i++) c[mt][nt][i] = 0.f;

    const int NC = Cv / BK;   // 32

    auto issue = [&](int ch) {
        if (ch < NC) {
            const int s = ch % NSTG;
            const float* gA = Ab + ch * BK;
            const float* gB = Bb + ch * BK;
            const uint32_t ab = aBase + (uint32_t)(s * TILEW * 4);
            const uint32_t bb = bBase + (uint32_t)(s * TILEW * 4);
            #pragma unroll
            for (int i = 0; i < 4; i++) {
                const int r = gr + i * 32;
                const uint32_t off = (uint32_t)((r * LDW + gc) * 4);
                cp_async16(ab + off, gA + (size_t)r * Cv + gc);
                cp_async16(bb + off, gB + (size_t)r * Cv + gc);
            }
        }
        asm volatile("cp.async.commit_group;" ::: "memory");
    };

    issue(0);
    issue(1);

    for (int ch = 0; ch < NC; ch++) {
        asm volatile("cp.async.wait_group 1;" ::: "memory");
        __syncthreads();
        issue(ch + 2);

        const int s = ch % NSTG;
        const uint32_t aStage = aFragBase + (uint32_t)(s * TILEW * 4);
        const uint32_t bStage = bFragBase + (uint32_t)(s * TILEW * 4);

        #pragma unroll
        for (int ks = 0; ks < 4; ks++) {
            uint32_t a[4][4];
            #pragma unroll
            for (int mt = 0; mt < 4; mt++)
                ldsm_x4(a[mt], aStage + (uint32_t)(mt * 16 * LDW * 4 + ks * 32));
            uint32_t b[2][4];
            #pragma unroll
            for (int ntp = 0; ntp < 2; ntp++)
                ldsm_x4(b[ntp], bStage + (uint32_t)(ntp * 16 * LDW * 4 + ks * 32));
            #pragma unroll
            for (int mt = 0; mt < 4; mt++)
                #pragma unroll
                for (int nt = 0; nt < 4; nt++)
                    mma16n8k8(c[mt][nt], a[mt], b[nt >> 1] + (nt & 1) * 2);
        }
    }

    #pragma unroll
    for (int mt = 0; mt < 4; mt++) {
        #pragma unroll
        for (int r2 = 0; r2 < 2; r2++) {
            const int row = row0 + wm + mt * 16 + g + r2 * 8;
            const int b_ = row >> 11, t_ = row & 2047;
            #pragma unroll
            for (int nt = 0; nt < 4; nt++) {
                const int col = col0 + wn + nt * 8 + tg * 2;
                float2 v;
                v.x = c[mt][nt][r2 * 2 + 0] + __ldg(bias + col + 0);
                v.y = c[mt][nt][r2 * 2 + 1] + __ldg(bias + col + 1);
                if (MODE == 0) {
                    v.x = rna_tf32(v.x);
                    v.y = rna_tf32(v.y);
                    const int which = col >> 10;
                    const int cc = col & 1023;
                    const int h = cc >> 6, d = cc & 63;
                    float* dst = (which == 0) ? g_q : (which == 1) ? g_k : g_v;
                    *(float2*)&dst[((size_t)((b_ * Hv + h) * Tv + t_)) * Dv + d] = v;
                } else {
                    *(float2*)&out[(size_t)row * Cv + col] = v;
                }
            }
        }
    }
}

// ---------------------------------------------------------------------------
// Flash attention — R14: persistent balanced schedule, 4 warps x 32 q-rows,
// exp2-domain softmax, KV cp.async double buffer, Q frags hoisted,
// QP smem reused as P staging.
// Grid = 296 CTAs; snake over weight-sorted jobs: p -> qtile 15-(p>>6), bh p&63.
// ---------------------------------------------------------------------------
#define ALD 68
#define VLD 72
#define KVSTG (64*ALD + 64*VLD)
#define ATTN_SMEM ((128*ALD + 2*KVSTG) * 4)   // 106496 B
#define NSLOTS 296

__global__ void __launch_bounds__(128) attn_mma_kernel()
{
    extern __shared__ float sm[];
    float* QP = sm;                    // [128][68]: Q then P staging
    float* KV = sm + 128 * ALD;

    const uint32_t qpBase = (uint32_t)__cvta_generic_to_shared(QP);
    const uint32_t kvBase = (uint32_t)__cvta_generic_to_shared(KV);

    const int tid  = threadIdx.x;
    const int lane = tid & 31;
    const int w    = tid >> 5;
    const int g    = lane >> 2;
    const int tg   = lane & 3;

    const int wrow = 32 * w;
    const int lrow  = lane & 15;
    const int lcolw = (lane >> 4) << 2;
    const int brow  = (lane & 7) + ((lane & 16) ? 8 : 0);
    const int bcolw = ((lane >> 3) & 1) << 2;
    const uint32_t pFragBase = qpBase + (uint32_t)(((wrow + lrow) * ALD + lcolw) * 4);

    const float QSCALE = 0.125f * 1.4426950408889634f;   // log2(e)/8

    #pragma unroll 1
    for (int r = 0; r < 4; r++) {
        const int p = r * NSLOTS + ((r & 1) ? (NSLOTS - 1 - (int)blockIdx.x)
                                            : (int)blockIdx.x);
        if (p >= 1024) continue;                 // uniform across the CTA
        const int m0 = (15 - (p >> 6)) * 128;    // q-tile (heavy first)
        const int bh = p & 63;

        const float* qp = g_q + (size_t)bh * Tv * Dv;
        const float* kp = g_k + (size_t)bh * Tv * Dv;
        const float* vp = g_v + (size_t)bh * Tv * Dv;

        auto issue_kv = [&](int kt) {
            const int s = kt & 1;
            const float* kpt = kp + (size_t)(kt * 64) * Dv;
            const float* vpt = vp + (size_t)(kt * 64) * Dv;
            const uint32_t kb = kvBase + (uint32_t)(s * KVSTG * 4);
            const uint32_t vb = kb + (uint32_t)(64 * ALD * 4);
            #pragma unroll
            for (int i = 0; i < 8; i++) {
                const int f = i * 128 + tid;
                const int rr = f >> 4, c4 = (f & 15) << 2;
                cp_async16(kb + (uint32_t)((rr * ALD + c4) * 4), kpt + rr * Dv + c4);
                cp_async16(vb + (uint32_t)((rr * VLD + c4) * 4), vpt + rr * Dv + c4);
            }
            asm volatile("cp.async.commit_group;" ::: "memory");
        };

        __syncthreads();   // previous tile's QP reads fully done before overwrite

        issue_kv(0);

        // Load Q tile, scale by log2(e)/8, re-round to tf32.
        #pragma unroll
        for (int i = 0; i < 16; i++) {
            const int f = i * 128 + tid;
            const int rr = f >> 4, c4 = (f & 15) << 2;
            float4 v = *(const float4*)(qp + (size_t)(m0 + rr) * Dv + c4);
            v.x = rna_tf32(v.x * QSCALE);
            v.y = rna_tf32(v.y * QSCALE);
            v.z = rna_tf32(v.z * QSCALE);
            v.w = rna_tf32(v.w * QSCALE);
            *(float4*)&QP[rr * ALD + c4] = v;
        }
        __syncthreads();

        // Hoist Q fragments; QP becomes P staging afterwards.
        uint32_t qf[2][8][4];
        #pragma unroll
        for (int ks = 0; ks < 8; ks++) {
            ldsm_x4(qf[0][ks], pFragBase + (uint32_t)(ks * 32));
            ldsm_x4(qf[1][ks], pFragBase + (uint32_t)(16 * ALD * 4 + ks * 32));
        }

        float m_i[4] = {-1e30f, -1e30f, -1e30f, -1e30f};
        float l_i[4] = {0.f, 0.f, 0.f, 0.f};
        float o[2][8][4];
        #pragma unroll
        for (int rc = 0; rc < 2; rc++)
            #pragma unroll
            for (int nt = 0; nt < 8; nt++)
                #pragma unroll
                for (int e = 0; e < 4; e++) o[rc][nt][e] = 0.f;

        const int nkt = m0 / 64 + 2;
        for (int kt = 0; kt < nkt; kt++) {
            const int j0 = kt * 64;
            asm volatile("cp.async.wait_group 0;" ::: "memory");
            __syncthreads();
            if (kt + 1 < nkt) issue_kv(kt + 1);

            const int s = kt & 1;
            const uint32_t kFragBase = kvBase + (uint32_t)(s * KVSTG * 4)
                                     + (uint32_t)((brow * ALD + bcolw) * 4);
            const uint32_t* Vsu = (const uint32_t*)(KV + s * KVSTG + 64 * ALD);

            // ---- S = Q @ K^T (log2 domain) ----
            float sacc[2][8][4];
            #pragma unroll
            for (int rc = 0; rc < 2; rc++)
                #pragma unroll
                for (int nt = 0; nt < 8; nt++)
                    #pragma unroll
                    for (int e = 0; e < 4; e++) sacc[rc][nt][e] = 0.f;

            #pragma unroll
            for (int ks = 0; ks < 8; ks++) {
                #pragma unroll
                for (int ntp = 0; ntp < 4; ntp++) {
                    uint32_t bb[4];
                    ldsm_x4(bb, kFragBase + (uint32_t)(ntp * 16 * ALD * 4 + ks * 32));
                    mma16n8k8(sacc[0][2 * ntp],     qf[0][ks], bb);
                    mma16n8k8(sacc[1][2 * ntp],     qf[1][ks], bb);
                    mma16n8k8(sacc[0][2 * ntp + 1], qf[0][ks], bb + 2);
                    mma16n8k8(sacc[1][2 * ntp + 1], qf[1][ks], bb + 2);
                }
            }

            // ---- causal mask ----
            if (j0 + 63 > m0 + wrow) {
                #pragma unroll
                for (int rc = 0; rc < 2; rc++)
                    #pragma unroll
                    for (int nt = 0; nt < 8; nt++)
                        #pragma unroll
                        for (int e = 0; e < 4; e++) {
                            const int row = m0 + wrow + 16 * rc + g + (e >> 1) * 8;
                            const int key = j0 + nt * 8 + 2 * tg + (e & 1);
                            if (key > row) sacc[rc][nt][e] = -1e30f;
                        }
            }

            // ---- online softmax (exp2 domain) ----
            #pragma unroll
            for (int rc = 0; rc < 2; rc++) {
                #pragma unroll
                for (int r2 = 0; r2 < 2; r2++) {
                    const int si = rc * 2 + r2;
                    float mx = -1e30f;
                    #pragma unroll
                    for (int nt = 0; nt < 8; nt++)
                        mx = fmaxf(mx, fmaxf(sacc[rc][nt][r2 * 2], sacc[rc][nt][r2 * 2 + 1]));
                    mx = fmaxf(mx, __shfl_xor_sync(0xffffffffu, mx, 1));
                    mx = fmaxf(mx, __shfl_xor_sync(0xffffffffu, mx, 2));
                    const float mn = fmaxf(m_i[si], mx);
                    const float corr = exp2f(m_i[si] - mn);
                    m_i[si] = mn;
                    float rs = 0.f;
                    #pragma unroll
                    for (int nt = 0; nt < 8; nt++) {
                        float p0 = exp2f(sacc[rc][nt][r2 * 2]     - mn);
                        float p1 = exp2f(sacc[rc][nt][r2 * 2 + 1] - mn);
                        sacc[rc][nt][r2 * 2]     = p0;
                        sacc[rc][nt][r2 * 2 + 1] = p1;
                        rs += p0 + p1;
                    }
                    rs += __shfl_xor_sync(0xffffffffu, rs, 1);
                    rs += __shfl_xor_sync(0xffffffffu, rs, 2);
                    l_i[si] = l_i[si] * corr + rs;
                    #pragma unroll
                    for (int nt = 0; nt < 8; nt++) {
                        o[rc][nt][r2 * 2]     *= corr;
                        o[rc][nt][r2 * 2 + 1] *= corr;
                    }
                }
            }

            // ---- stage P into QP (warp-private rows) ----
            {
                float* Ps = QP;
                #pragma unroll
                for (int rc = 0; rc < 2; rc++) {
                    const int rr = wrow + 16 * rc + g;
                    #pragma unroll
                    for (int nt = 0; nt < 8; nt++) {
                        *(float2*)&Ps[rr * ALD + nt * 8 + 2 * tg] =
                            make_float2(rna_tf32(sacc[rc][nt][0]), rna_tf32(sacc[rc][nt][1]));
                        *(float2*)&Ps[(rr + 8) * ALD + nt * 8 + 2 * tg] =
                            make_float2(rna_tf32(sacc[rc][nt][2]), rna_tf32(sacc[rc][nt][3]));
                    }
                }
            }
            __syncwarp();

            // ---- O += P @ V ----
            #pragma unroll
            for (int ks = 0; ks < 8; ks++) {
                const int kk = ks * 8 + tg;
                uint32_t a[2][4];
                ldsm_x4(a[0], pFragBase + (uint32_t)(ks * 32));
                ldsm_x4(a[1], pFragBase + (uint32_t)(16 * ALD * 4 + ks * 32));
                #pragma unroll
                for (int nt = 0; nt < 8; nt++) {
                    uint32_t b[2];
                    b[0] = Vsu[kk * VLD + nt * 8 + g];
                    b[1] = Vsu[(kk + 4) * VLD + nt * 8 + g];
                    mma16n8k8(o[0][nt], a[0], b);
                    mma16n8k8(o[1][nt], a[1], b);
                }
            }
            __syncwarp();
        }

        // ---- normalize, round to tf32 (gemm<1> operand), write g_y ----
        const int b_ = bh >> 4;
        const int head = bh & 15;
        #pragma unroll
        for (int rc = 0; rc < 2; rc++) {
            #pragma unroll
            for (int r2 = 0; r2 < 2; r2++) {
                const float inv = 1.f / l_i[rc * 2 + r2];
                const int row = m0 + wrow + 16 * rc + g + r2 * 8;
                #pragma unroll
                for (int nt = 0; nt < 8; nt++) {
                    float2 v;
                    v.x = rna_tf32(o[rc][nt][r2 * 2]     * inv);
                    v.y = rna_tf32(o[rc][nt][r2 * 2 + 1] * inv);
                    *(float2*)&g_y[((size_t)(b_ * Tv + row)) * Cv + head * 64 + nt * 8 + 2 * tg] = v;
                }
            }
        }
    }
}

// ---------------------------------------------------------------------------
extern "C" void kernel_launch(void* const* d_in, const int* in_sizes, int n_in,
                              void* d_out, int out_size)
{
    const float* x     = (const float*)d_in[0];
    const float* W_qkv = (const float*)d_in[1];
    const float* b_qkv = (const float*)d_in[2];
    const float* W_out = (const float*)d_in[3];
    const float* b_out = (const float*)d_in[4];
    float* out = (float*)d_out;

    float* xr;  cudaGetSymbolAddress((void**)&xr,  g_xr);
    float* wqT; cudaGetSymbolAddress((void**)&wqT, g_wqT);
    float* woT; cudaGetSymbolAddress((void**)&woT, g_woT);

    cudaFuncSetAttribute(attn_mma_kernel,
                         cudaFuncAttributeMaxDynamicSharedMemorySize, ATTN_SMEM);
    cudaFuncSetAttribute(gemm_mma<0>,
                         cudaFuncAttributeMaxDynamicSharedMemorySize, GEMM_SMEM);
    cudaFuncSetAttribute(gemm_mma<1>,
                         cudaFuncAttributeMaxDynamicSharedMemorySize, GEMM_SMEM);

    // prep: single launch — round x; transpose+round both weights
    prep_kernel<<<5120, 256>>>(x, W_qkv, W_out);

    // 1) QKV projection (R9 config: 3-stage, 2 CTAs/SM)
    gemm_mma<0><<<dim3(3 * Cv / 128, Mrows / 128), 256, GEMM_SMEM>>>(xr, wqT, b_qkv, nullptr);

    // 2) causal flash attention — persistent balanced schedule (296 CTAs)
    attn_mma_kernel<<<dim3(NSLOTS, 1), 128, ATTN_SMEM>>>();

    // 3) output projection
    gemm_mma<1><<<dim3(Cv / 128, Mrows / 128), 256, GEMM_SMEM>>>(nullptr, woT, b_out, out);
}